// round 1
// baseline (speedup 1.0000x reference)
#include <cuda_runtime.h>
#include <math.h>

#define NN 100000
#define EE 600000
#define CC 128
#define FIN 64
#define OO 8
#define NEG 0.2f

// ---------------- scratch (device globals; no runtime allocation) ----------------
__device__ float g_h[NN * CC];        // projected features
__device__ float g_att[NN * 8];       // per node: a_src[t0h0,t0h1,t1h0,t1h1], a_dst[...]
__device__ float g_out0[NN * CC];     // edge-type 0 output
__device__ float g_out1[NN * CC];     // edge-type 1 output
__device__ float g_comb[NN * CC];     // combined layer output (input to next layer)
__device__ int   g_cnt[2 * NN];       // per-dst degree histogram
__device__ int   g_rowptr[2 * (NN + 1)];
__device__ int   g_off[2 * NN];       // scatter cursors
__device__ int   g_esrc[2 * EE];      // src ids sorted by dst (CSR payload)
__device__ float g_scores[4];         // semantic scores: layer1 [0,1], layer2 [2,3]

// ---------------- helpers ----------------
__device__ __forceinline__ float warp_sum(float v) {
#pragma unroll
    for (int o = 16; o > 0; o >>= 1) v += __shfl_xor_sync(0xffffffffu, v, o);
    return v;
}
__device__ __forceinline__ float warp_max(float v) {
#pragma unroll
    for (int o = 16; o > 0; o >>= 1) v = fmaxf(v, __shfl_xor_sync(0xffffffffu, v, o));
    return v;
}
__device__ __forceinline__ float leaky(float x) { return x > 0.f ? x : NEG * x; }

// ---------------- CSR build ----------------
__global__ void zero_kernel() {
    int i = blockIdx.x * blockDim.x + threadIdx.x;
    if (i < 2 * NN) g_cnt[i] = 0;
    if (i < 4) g_scores[i] = 0.f;
}

__global__ void hist_kernel(const int* __restrict__ ei0, const int* __restrict__ ei1) {
    int i = blockIdx.x * blockDim.x + threadIdx.x;
    if (i >= 2 * EE) return;
    int t = i / EE, e = i - t * EE;
    const int* ei = t ? ei1 : ei0;
    atomicAdd(&g_cnt[t * NN + ei[EE + e]], 1);
}

// one block per edge type; 1024 threads, chunked sequential + Hillis-Steele scan
__global__ void scan_kernel() {
    const int t = blockIdx.x;
    const int tid = threadIdx.x;
    const int CH = (NN + 1023) / 1024;  // 98
    int start = tid * CH;
    int end = min(start + CH, NN);
    int s = 0;
    for (int i = start; i < end; i++) s += g_cnt[t * NN + i];
    __shared__ int sums[1024];
    sums[tid] = s;
    __syncthreads();
    for (int off = 1; off < 1024; off <<= 1) {
        int v = (tid >= off) ? sums[tid - off] : 0;
        __syncthreads();
        sums[tid] += v;
        __syncthreads();
    }
    int run = sums[tid] - s;  // exclusive base for this chunk
    for (int i = start; i < end; i++) {
        g_rowptr[t * (NN + 1) + i] = run;
        g_off[t * NN + i] = run;
        run += g_cnt[t * NN + i];
    }
    if (tid == 1023) g_rowptr[t * (NN + 1) + NN] = sums[1023];
}

__global__ void scatter_kernel(const int* __restrict__ ei0, const int* __restrict__ ei1) {
    int i = blockIdx.x * blockDim.x + threadIdx.x;
    if (i >= 2 * EE) return;
    int t = i / EE, e = i - t * EE;
    const int* ei = t ? ei1 : ei0;
    int dst = ei[EE + e];
    int pos = atomicAdd(&g_off[t * NN + dst], 1);
    g_esrc[t * EE + pos] = ei[e];
}

// ---------------- projection GEMM: g_h = A @ W + bias  (A: [NN,K], W: [K,128]) ----------------
template <int K>
__global__ __launch_bounds__(256) void proj_kernel(const float* __restrict__ Ain,
                                                   const float* __restrict__ W,
                                                   const float* __restrict__ bias) {
    const float* A = Ain ? Ain : g_comb;
    __shared__ float As[16][64];
    __shared__ float Bs[16][128];
    const int tid = threadIdx.x;
    const int row0 = blockIdx.x * 64;
    const int tm = tid >> 5;            // 0..7 (row group)
    const int tn = tid & 31;            // 0..31 (col group of 4)
    const int lr = tid >> 2;            // 0..63 A-load row
    const int lk4 = (tid & 3) * 4;      // A-load k quad
    const int bk = tid >> 4;            // 0..15 B-load row
    const int bc = (tid & 15) * 8;      // B-load col base

    float acc[8][4];
#pragma unroll
    for (int i = 0; i < 8; i++)
#pragma unroll
        for (int j = 0; j < 4; j++) acc[i][j] = 0.f;

    for (int k0 = 0; k0 < K; k0 += 16) {
        float4 av = make_float4(0.f, 0.f, 0.f, 0.f);
        int r = row0 + lr;
        if (r < NN) av = *reinterpret_cast<const float4*>(A + (size_t)r * K + k0 + lk4);
        As[lk4 + 0][lr] = av.x;
        As[lk4 + 1][lr] = av.y;
        As[lk4 + 2][lr] = av.z;
        As[lk4 + 3][lr] = av.w;
        float4 b0 = *reinterpret_cast<const float4*>(W + (size_t)(k0 + bk) * CC + bc);
        float4 b1 = *reinterpret_cast<const float4*>(W + (size_t)(k0 + bk) * CC + bc + 4);
        *reinterpret_cast<float4*>(&Bs[bk][bc]) = b0;
        *reinterpret_cast<float4*>(&Bs[bk][bc + 4]) = b1;
        __syncthreads();
#pragma unroll
        for (int k = 0; k < 16; k++) {
            float4 a0 = *reinterpret_cast<const float4*>(&As[k][tm * 8]);
            float4 a1 = *reinterpret_cast<const float4*>(&As[k][tm * 8 + 4]);
            float4 b = *reinterpret_cast<const float4*>(&Bs[k][tn * 4]);
            float a[8] = {a0.x, a0.y, a0.z, a0.w, a1.x, a1.y, a1.z, a1.w};
            float bb[4] = {b.x, b.y, b.z, b.w};
#pragma unroll
            for (int i = 0; i < 8; i++)
#pragma unroll
                for (int j = 0; j < 4; j++) acc[i][j] += a[i] * bb[j];
        }
        __syncthreads();
    }
    float4 bv = *reinterpret_cast<const float4*>(bias + tn * 4);
#pragma unroll
    for (int i = 0; i < 8; i++) {
        int r = row0 + tm * 8 + i;
        if (r < NN) {
            float4 o;
            o.x = acc[i][0] + bv.x;
            o.y = acc[i][1] + bv.y;
            o.z = acc[i][2] + bv.z;
            o.w = acc[i][3] + bv.w;
            *reinterpret_cast<float4*>(g_h + (size_t)r * CC + tn * 4) = o;
        }
    }
}

// ---------------- per-node attention dot products ----------------
__global__ void att_kernel(const float* __restrict__ as_, const float* __restrict__ ad_) {
    int wid = threadIdx.x >> 5, lane = threadIdx.x & 31;
    int n = blockIdx.x * 8 + wid;
    if (n >= NN) return;
    const float* hr = g_h + (size_t)n * CC;
    float v0 = hr[lane], v1 = hr[32 + lane], v2 = hr[64 + lane], v3 = hr[96 + lane];
    float r[8];
    r[0] = v0 * as_[lane] + v1 * as_[32 + lane];
    r[1] = v2 * as_[64 + lane] + v3 * as_[96 + lane];
    r[2] = v0 * as_[128 + lane] + v1 * as_[160 + lane];
    r[3] = v2 * as_[192 + lane] + v3 * as_[224 + lane];
    r[4] = v0 * ad_[lane] + v1 * ad_[32 + lane];
    r[5] = v2 * ad_[64 + lane] + v3 * ad_[96 + lane];
    r[6] = v0 * ad_[128 + lane] + v1 * ad_[160 + lane];
    r[7] = v2 * ad_[192 + lane] + v3 * ad_[224 + lane];
#pragma unroll
    for (int k = 0; k < 8; k++) r[k] = warp_sum(r[k]);
    if (lane == 0) {
#pragma unroll
        for (int k = 0; k < 8; k++) g_att[n * 8 + k] = r[k];
    }
}

// ---------------- edge softmax + aggregation (atomic-free, warp per dst node) ----------------
__global__ void agg_kernel(int t) {
    int wid = threadIdx.x >> 5, lane = threadIdx.x & 31;
    int n = blockIdx.x * 8 + wid;
    if (n >= NN) return;
    float* outp = t ? g_out1 : g_out0;
    int base = g_rowptr[t * (NN + 1) + n];
    int deg = g_rowptr[t * (NN + 1) + n + 1] - base;
    float ad0 = g_att[n * 8 + 4 + 2 * t];
    float ad1 = g_att[n * 8 + 5 + 2 * t];

    // pass 1: per-head max (lanes parallel over edges)
    float m0 = -3.0e38f, m1 = -3.0e38f;
    for (int j = lane; j < deg; j += 32) {
        int src = g_esrc[t * EE + base + j];
        float a0 = leaky(g_att[src * 8 + 2 * t] + ad0);
        float a1 = leaky(g_att[src * 8 + 2 * t + 1] + ad1);
        m0 = fmaxf(m0, a0);
        m1 = fmaxf(m1, a1);
    }
    m0 = warp_max(m0);
    m1 = warp_max(m1);

    // pass 2: exp-weighted accumulation (whole warp per edge, coalesced row reads)
    float s0 = 0.f, s1 = 0.f;
    float acc0 = 0.f, acc1 = 0.f, acc2 = 0.f, acc3 = 0.f;
    for (int j = 0; j < deg; j++) {
        int src = g_esrc[t * EE + base + j];
        float w0 = expf(leaky(g_att[src * 8 + 2 * t] + ad0) - m0);
        float w1 = expf(leaky(g_att[src * 8 + 2 * t + 1] + ad1) - m1);
        s0 += w0;
        s1 += w1;
        const float* hr = g_h + (size_t)src * CC;
        acc0 += w0 * hr[lane];
        acc1 += w0 * hr[32 + lane];
        acc2 += w1 * hr[64 + lane];
        acc3 += w1 * hr[96 + lane];
    }
    float r0 = 1.f / (s0 + 1e-16f);
    float r1 = 1.f / (s1 + 1e-16f);
    float* orow = outp + (size_t)n * CC;
    orow[lane] = fmaxf(acc0 * r0, 0.f);
    orow[32 + lane] = fmaxf(acc1 * r0, 0.f);
    orow[64 + lane] = fmaxf(acc2 * r1, 0.f);
    orow[96 + lane] = fmaxf(acc3 * r1, 0.f);
}

// ---------------- semantic attention score: sum_n q . tanh(out_t @ kw + kb) ----------------
__global__ __launch_bounds__(256) void sem_kernel(const float* __restrict__ kw,
                                                  const float* __restrict__ kb,
                                                  const float* __restrict__ q,
                                                  int sbase) {
    const float* A = blockIdx.y ? g_out1 : g_out0;
    __shared__ float As[16][64];
    __shared__ float Bs[16][128];
    const int tid = threadIdx.x;
    const int row0 = blockIdx.x * 64;
    const int tm = tid >> 5;
    const int tn = tid & 31;
    const int lr = tid >> 2;
    const int lk4 = (tid & 3) * 4;
    const int bk = tid >> 4;
    const int bc = (tid & 15) * 8;

    float acc[8][4];
#pragma unroll
    for (int i = 0; i < 8; i++)
#pragma unroll
        for (int j = 0; j < 4; j++) acc[i][j] = 0.f;

    for (int k0 = 0; k0 < CC; k0 += 16) {
        float4 av = make_float4(0.f, 0.f, 0.f, 0.f);
        int r = row0 + lr;
        if (r < NN) av = *reinterpret_cast<const float4*>(A + (size_t)r * CC + k0 + lk4);
        As[lk4 + 0][lr] = av.x;
        As[lk4 + 1][lr] = av.y;
        As[lk4 + 2][lr] = av.z;
        As[lk4 + 3][lr] = av.w;
        float4 b0 = *reinterpret_cast<const float4*>(kw + (size_t)(k0 + bk) * CC + bc);
        float4 b1 = *reinterpret_cast<const float4*>(kw + (size_t)(k0 + bk) * CC + bc + 4);
        *reinterpret_cast<float4*>(&Bs[bk][bc]) = b0;
        *reinterpret_cast<float4*>(&Bs[bk][bc + 4]) = b1;
        __syncthreads();
#pragma unroll
        for (int k = 0; k < 16; k++) {
            float4 a0 = *reinterpret_cast<const float4*>(&As[k][tm * 8]);
            float4 a1 = *reinterpret_cast<const float4*>(&As[k][tm * 8 + 4]);
            float4 b = *reinterpret_cast<const float4*>(&Bs[k][tn * 4]);
            float a[8] = {a0.x, a0.y, a0.z, a0.w, a1.x, a1.y, a1.z, a1.w};
            float bb[4] = {b.x, b.y, b.z, b.w};
#pragma unroll
            for (int i = 0; i < 8; i++)
#pragma unroll
                for (int j = 0; j < 4; j++) acc[i][j] += a[i] * bb[j];
        }
        __syncthreads();
    }
    float local = 0.f;
#pragma unroll
    for (int i = 0; i < 8; i++) {
        int r = row0 + tm * 8 + i;
        if (r < NN) {
#pragma unroll
            for (int j = 0; j < 4; j++) {
                int c = tn * 4 + j;
                local += q[c] * tanhf(acc[i][j] + kb[c]);
            }
        }
    }
    local = warp_sum(local);
    __shared__ float wsum[8];
    if ((tid & 31) == 0) wsum[tm] = local;
    __syncthreads();
    if (tid == 0) {
        float tot = 0.f;
#pragma unroll
        for (int k = 0; k < 8; k++) tot += wsum[k];
        atomicAdd(&g_scores[sbase + blockIdx.y], tot);
    }
}

// ---------------- weighted combine + ReLU ----------------
__global__ void combine_kernel(int sbase) {
    int idx = blockIdx.x * blockDim.x + threadIdx.x;
    if (idx >= NN * CC / 4) return;
    float s0 = g_scores[sbase] * (1.f / NN);
    float s1 = g_scores[sbase + 1] * (1.f / NN);
    float m = fmaxf(s0, s1);
    float e0 = expf(s0 - m), e1 = expf(s1 - m);
    float a0 = e0 / (e0 + e1);
    float a1 = 1.f - a0;
    float4 v0 = reinterpret_cast<const float4*>(g_out0)[idx];
    float4 v1 = reinterpret_cast<const float4*>(g_out1)[idx];
    float4 r;
    r.x = fmaxf(a0 * v0.x + a1 * v1.x, 0.f);
    r.y = fmaxf(a0 * v0.y + a1 * v1.y, 0.f);
    r.z = fmaxf(a0 * v0.z + a1 * v1.z, 0.f);
    r.w = fmaxf(a0 * v0.w + a1 * v1.w, 0.f);
    reinterpret_cast<float4*>(g_comb)[idx] = r;
}

// ---------------- final linear ----------------
__global__ void final_kernel(const float* __restrict__ lw, const float* __restrict__ lb,
                             float* __restrict__ out) {
    int i = blockIdx.x * blockDim.x + threadIdx.x;
    if (i >= NN * OO) return;
    int n = i >> 3, o = i & 7;
    float acc = lb[o];
    const float* row = g_comb + (size_t)n * CC;
#pragma unroll 8
    for (int c = 0; c < CC; c++) acc += row[c] * lw[c * OO + o];
    out[i] = acc;
}

// ---------------- launch ----------------
extern "C" void kernel_launch(void* const* d_in, const int* in_sizes, int n_in,
                              void* d_out, int out_size) {
    const float *x = 0, *p1w = 0, *p1b = 0, *p1as = 0, *p1ad = 0, *p1q = 0, *p1kw = 0, *p1kb = 0;
    const float *p2w = 0, *p2b = 0, *p2as = 0, *p2ad = 0, *p2q = 0, *p2kw = 0, *p2kb = 0;
    const float *linw = 0, *linb = 0;
    const int *ei0 = 0, *ei1 = 0;
    int nEi = 0, n16k = 0, n256 = 0, n128 = 0;
    for (int i = 0; i < n_in; i++) {
        const float* fp = (const float*)d_in[i];
        switch (in_sizes[i]) {
            case NN * FIN: x = fp; break;                       // 6,400,000
            case 2 * EE:                                        // 1,200,000 ints
                if (nEi == 0) ei0 = (const int*)d_in[i];
                else ei1 = (const int*)d_in[i];
                nEi++;
                break;
            case FIN * CC: p1w = fp; break;                     // 8192
            case CC * CC:                                       // 16384: p1_kw, p2_proj_w, p2_kw
                if (n16k == 0) p1kw = fp;
                else if (n16k == 1) p2w = fp;
                else p2kw = fp;
                n16k++;
                break;
            case 256:                                           // att vectors, in order
                if (n256 == 0) p1as = fp;
                else if (n256 == 1) p1ad = fp;
                else if (n256 == 2) p2as = fp;
                else p2ad = fp;
                n256++;
                break;
            case CC:                                            // 128: p1_b, p1_q, p1_kb, p2_b, p2_q, p2_kb
                if (n128 == 0) p1b = fp;
                else if (n128 == 1) p1q = fp;
                else if (n128 == 2) p1kb = fp;
                else if (n128 == 3) p2b = fp;
                else if (n128 == 4) p2q = fp;
                else p2kb = fp;
                n128++;
                break;
            case CC * OO: linw = fp; break;                     // 1024
            case OO: linb = fp; break;                          // 8
            default: break;
        }
    }

    const int GRID_GEMM = (NN + 63) / 64;       // 1563
    const int GRID_NODE = (NN + 7) / 8;         // 12500 (warp per node)
    const int GRID_EDGE = (2 * EE + 255) / 256; // 4688

    // CSR build (edges are the same for both layers)
    zero_kernel<<<(2 * NN + 255) / 256, 256>>>();
    hist_kernel<<<GRID_EDGE, 256>>>(ei0, ei1);
    scan_kernel<<<2, 1024>>>();
    scatter_kernel<<<GRID_EDGE, 256>>>(ei0, ei1);

    // ---- layer 1 ----
    proj_kernel<FIN><<<GRID_GEMM, 256>>>(x, p1w, p1b);
    att_kernel<<<GRID_NODE, 256>>>(p1as, p1ad);
    agg_kernel<<<GRID_NODE, 256>>>(0);
    agg_kernel<<<GRID_NODE, 256>>>(1);
    sem_kernel<<<dim3(GRID_GEMM, 2), 256>>>(p1kw, p1kb, p1q, 0);
    combine_kernel<<<(NN * CC / 4 + 255) / 256, 256>>>(0);

    // ---- layer 2 ----
    proj_kernel<CC><<<GRID_GEMM, 256>>>(nullptr, p2w, p2b);  // A = g_comb
    att_kernel<<<GRID_NODE, 256>>>(p2as, p2ad);
    agg_kernel<<<GRID_NODE, 256>>>(0);
    agg_kernel<<<GRID_NODE, 256>>>(1);
    sem_kernel<<<dim3(GRID_GEMM, 2), 256>>>(p2kw, p2kb, p2q, 2);
    combine_kernel<<<(NN * CC / 4 + 255) / 256, 256>>>(2);

    // ---- classifier ----
    final_kernel<<<(NN * OO + 255) / 256, 256>>>(linw, linb, (float*)d_out);
}

// round 2
// speedup vs baseline: 1.2305x; 1.2305x over previous
#include <cuda_runtime.h>
#include <math.h>

#define NN 100000
#define EE 600000
#define CC 128
#define FIN 64
#define OO 8
#define NEG 0.2f

// ---------------- scratch (device globals; no runtime allocation) ----------------
__device__ float g_h[NN * CC];
__device__ float g_att[NN * 8];
__device__ float g_out0[NN * CC];
__device__ float g_out1[NN * CC];
__device__ float g_comb[NN * CC];
__device__ int   g_cnt[2 * NN];
__device__ int   g_rowptr[2 * (NN + 1)];
__device__ int   g_off[2 * NN];
__device__ int   g_esrc[2 * EE];
__device__ float g_scores[4];

// ---------------- helpers ----------------
__device__ __forceinline__ float warp_sum(float v) {
#pragma unroll
    for (int o = 16; o > 0; o >>= 1) v += __shfl_xor_sync(0xffffffffu, v, o);
    return v;
}
__device__ __forceinline__ float warp_max(float v) {
#pragma unroll
    for (int o = 16; o > 0; o >>= 1) v = fmaxf(v, __shfl_xor_sync(0xffffffffu, v, o));
    return v;
}
__device__ __forceinline__ float leaky(float x) { return x > 0.f ? x : NEG * x; }

__device__ __forceinline__ unsigned f2tf(float x) {
    unsigned r;
    asm("cvt.rna.tf32.f32 %0, %1;" : "=r"(r) : "f"(x));
    return r;
}
__device__ __forceinline__ void split_tf(float v, unsigned& hi, unsigned& lo) {
    unsigned h = f2tf(v);
    hi = h;
    lo = f2tf(v - __uint_as_float(h));
}
__device__ __forceinline__ void mma8(float* c, const unsigned* a, const unsigned* b) {
    asm volatile(
        "mma.sync.aligned.m16n8k8.row.col.f32.tf32.tf32.f32 "
        "{%0,%1,%2,%3},{%4,%5,%6,%7},{%8,%9},{%0,%1,%2,%3};\n"
        : "+f"(c[0]), "+f"(c[1]), "+f"(c[2]), "+f"(c[3])
        : "r"(a[0]), "r"(a[1]), "r"(a[2]), "r"(a[3]), "r"(b[0]), "r"(b[1]));
}

// ---------------- CSR build ----------------
__global__ void zero_kernel() {
    int i = blockIdx.x * blockDim.x + threadIdx.x;
    if (i < 2 * NN) g_cnt[i] = 0;
    if (i < 4) g_scores[i] = 0.f;
}

__global__ void hist_kernel(const int* __restrict__ ei0, const int* __restrict__ ei1) {
    int i = blockIdx.x * blockDim.x + threadIdx.x;
    if (i >= 2 * EE) return;
    int t = i / EE, e = i - t * EE;
    const int* ei = t ? ei1 : ei0;
    atomicAdd(&g_cnt[t * NN + ei[EE + e]], 1);
}

__global__ void scan_kernel() {
    const int t = blockIdx.x;
    const int tid = threadIdx.x;
    const int CH = (NN + 1023) / 1024;
    int start = tid * CH;
    int end = min(start + CH, NN);
    int s = 0;
    for (int i = start; i < end; i++) s += g_cnt[t * NN + i];
    __shared__ int sums[1024];
    sums[tid] = s;
    __syncthreads();
    for (int off = 1; off < 1024; off <<= 1) {
        int v = (tid >= off) ? sums[tid - off] : 0;
        __syncthreads();
        sums[tid] += v;
        __syncthreads();
    }
    int run = sums[tid] - s;
    for (int i = start; i < end; i++) {
        g_rowptr[t * (NN + 1) + i] = run;
        g_off[t * NN + i] = run;
        run += g_cnt[t * NN + i];
    }
    if (tid == 1023) g_rowptr[t * (NN + 1) + NN] = sums[1023];
}

__global__ void scatter_kernel(const int* __restrict__ ei0, const int* __restrict__ ei1) {
    int i = blockIdx.x * blockDim.x + threadIdx.x;
    if (i >= 2 * EE) return;
    int t = i / EE, e = i - t * EE;
    const int* ei = t ? ei1 : ei0;
    int dst = ei[EE + e];
    int pos = atomicAdd(&g_off[t * NN + dst], 1);
    g_esrc[t * EE + pos] = ei[e];
}

// ---------------- unified tensor-core GEMM ----------------
// C[NN,128] = A[NN,K] @ W[K,128]
// MODE 0: write g_h + bias (bk = bias).  PRECISE=1 -> 3xTF32 (near-fp32).
// MODE 1: semantic score: atomicAdd(sum_n q . tanh(row + kb)) ; A = g_out{y}.
template <int K, int MODE, int PRECISE>
__global__ __launch_bounds__(256) void mm_kernel(const float* __restrict__ Ain,
                                                 const float* __restrict__ W,
                                                 const float* __restrict__ bk,
                                                 const float* __restrict__ q,
                                                 int sidx) {
    const float* A;
    if (MODE == 1) A = blockIdx.y ? g_out1 : g_out0;
    else A = Ain ? Ain : g_comb;

    __shared__ float As[2][128][20];   // [m][k], stride 20 -> conflict-free frags
    __shared__ float Bs[2][16][136];   // [k][n], stride 136 -> conflict-free frags
    __shared__ float red[8];

    const int tid = threadIdx.x;
    const int row0 = blockIdx.x * 128;
    const int lane = tid & 31, wid = tid >> 5;
    const int wm = wid & 3, wn = wid >> 2;     // warp tile: 32 rows x 64 cols
    const int gid = lane >> 2, tig = lane & 3;
    const int NKC = K / 16;

    float acc[2][8][4];
#pragma unroll
    for (int mt = 0; mt < 2; mt++)
#pragma unroll
        for (int nt = 0; nt < 8; nt++)
#pragma unroll
            for (int e = 0; e < 4; e++) acc[mt][nt][e] = 0.f;

    const int ar = tid >> 2;          // A-load row 0..63 (+64)
    const int ak = (tid & 3) * 4;     // A-load k quad
    const int bkr = tid >> 5;         // B-load k 0..7 (+8)
    const int bc = (tid & 31) * 4;    // B-load col quad

    float4 pa[2], pb[2];
    // load chunk 0
#pragma unroll
    for (int i = 0; i < 2; i++) {
        int r = row0 + ar + 64 * i;
        pa[i] = (r < NN) ? *reinterpret_cast<const float4*>(A + (size_t)r * K + ak)
                         : make_float4(0.f, 0.f, 0.f, 0.f);
        pb[i] = *reinterpret_cast<const float4*>(W + (size_t)(bkr + 8 * i) * CC + bc);
    }
#pragma unroll
    for (int i = 0; i < 2; i++) {
        *reinterpret_cast<float4*>(&As[0][ar + 64 * i][ak]) = pa[i];
        *reinterpret_cast<float4*>(&Bs[0][bkr + 8 * i][bc]) = pb[i];
    }
    __syncthreads();

    int buf = 0;
    for (int ch = 0; ch < NKC; ch++) {
        if (ch + 1 < NKC) {
            int k0 = (ch + 1) * 16;
#pragma unroll
            for (int i = 0; i < 2; i++) {
                int r = row0 + ar + 64 * i;
                pa[i] = (r < NN)
                            ? *reinterpret_cast<const float4*>(A + (size_t)r * K + k0 + ak)
                            : make_float4(0.f, 0.f, 0.f, 0.f);
                pb[i] = *reinterpret_cast<const float4*>(W + (size_t)(k0 + bkr + 8 * i) * CC + bc);
            }
        }
#pragma unroll
        for (int ks = 0; ks < 16; ks += 8) {
            if (PRECISE) {
                unsigned ahi[2][4], alo[2][4];
#pragma unroll
                for (int mt = 0; mt < 2; mt++) {
                    int rb = wm * 32 + mt * 16 + gid;
                    split_tf(As[buf][rb][ks + tig], ahi[mt][0], alo[mt][0]);
                    split_tf(As[buf][rb + 8][ks + tig], ahi[mt][1], alo[mt][1]);
                    split_tf(As[buf][rb][ks + tig + 4], ahi[mt][2], alo[mt][2]);
                    split_tf(As[buf][rb + 8][ks + tig + 4], ahi[mt][3], alo[mt][3]);
                }
#pragma unroll
                for (int nt = 0; nt < 8; nt++) {
                    int cb = wn * 64 + nt * 8 + gid;
                    unsigned bhi[2], blo[2];
                    split_tf(Bs[buf][ks + tig][cb], bhi[0], blo[0]);
                    split_tf(Bs[buf][ks + tig + 4][cb], bhi[1], blo[1]);
#pragma unroll
                    for (int mt = 0; mt < 2; mt++) {
                        mma8(acc[mt][nt], ahi[mt], blo);
                        mma8(acc[mt][nt], alo[mt], bhi);
                        mma8(acc[mt][nt], ahi[mt], bhi);
                    }
                }
            } else {
                unsigned af[2][4];
#pragma unroll
                for (int mt = 0; mt < 2; mt++) {
                    int rb = wm * 32 + mt * 16 + gid;
                    af[mt][0] = f2tf(As[buf][rb][ks + tig]);
                    af[mt][1] = f2tf(As[buf][rb + 8][ks + tig]);
                    af[mt][2] = f2tf(As[buf][rb][ks + tig + 4]);
                    af[mt][3] = f2tf(As[buf][rb + 8][ks + tig + 4]);
                }
#pragma unroll
                for (int nt = 0; nt < 8; nt++) {
                    int cb = wn * 64 + nt * 8 + gid;
                    unsigned bf[2];
                    bf[0] = f2tf(Bs[buf][ks + tig][cb]);
                    bf[1] = f2tf(Bs[buf][ks + tig + 4][cb]);
#pragma unroll
                    for (int mt = 0; mt < 2; mt++) mma8(acc[mt][nt], af[mt], bf);
                }
            }
        }
        if (ch + 1 < NKC) {
#pragma unroll
            for (int i = 0; i < 2; i++) {
                *reinterpret_cast<float4*>(&As[buf ^ 1][ar + 64 * i][ak]) = pa[i];
                *reinterpret_cast<float4*>(&Bs[buf ^ 1][bkr + 8 * i][bc]) = pb[i];
            }
            __syncthreads();
            buf ^= 1;
        }
    }

    if (MODE == 0) {
#pragma unroll
        for (int nt = 0; nt < 8; nt++) {
            int c = wn * 64 + nt * 8 + 2 * tig;
            float b0 = bk[c], b1 = bk[c + 1];
#pragma unroll
            for (int mt = 0; mt < 2; mt++) {
                int r = row0 + wm * 32 + mt * 16 + gid;
                if (r < NN) {
                    float2 o = {acc[mt][nt][0] + b0, acc[mt][nt][1] + b1};
                    *reinterpret_cast<float2*>(g_h + (size_t)r * CC + c) = o;
                }
                if (r + 8 < NN) {
                    float2 o = {acc[mt][nt][2] + b0, acc[mt][nt][3] + b1};
                    *reinterpret_cast<float2*>(g_h + (size_t)(r + 8) * CC + c) = o;
                }
            }
        }
    } else {
        float local = 0.f;
#pragma unroll
        for (int nt = 0; nt < 8; nt++) {
            int c = wn * 64 + nt * 8 + 2 * tig;
            float q0 = q[c], q1 = q[c + 1];
            float k0v = bk[c], k1v = bk[c + 1];
#pragma unroll
            for (int mt = 0; mt < 2; mt++) {
                int r = row0 + wm * 32 + mt * 16 + gid;
                if (r < NN)
                    local += q0 * tanhf(acc[mt][nt][0] + k0v) + q1 * tanhf(acc[mt][nt][1] + k1v);
                if (r + 8 < NN)
                    local += q0 * tanhf(acc[mt][nt][2] + k0v) + q1 * tanhf(acc[mt][nt][3] + k1v);
            }
        }
        local = warp_sum(local);
        if (lane == 0) red[wid] = local;
        __syncthreads();
        if (tid == 0) {
            float t = 0.f;
#pragma unroll
            for (int k = 0; k < 8; k++) t += red[k];
            atomicAdd(&g_scores[sidx + blockIdx.y], t);
        }
    }
}

// ---------------- per-node attention dot products ----------------
__global__ void att_kernel(const float* __restrict__ as_, const float* __restrict__ ad_) {
    int wid = threadIdx.x >> 5, lane = threadIdx.x & 31;
    int n = blockIdx.x * 8 + wid;
    if (n >= NN) return;
    const float* hr = g_h + (size_t)n * CC;
    float v0 = hr[lane], v1 = hr[32 + lane], v2 = hr[64 + lane], v3 = hr[96 + lane];
    float r[8];
    r[0] = v0 * as_[lane] + v1 * as_[32 + lane];
    r[1] = v2 * as_[64 + lane] + v3 * as_[96 + lane];
    r[2] = v0 * as_[128 + lane] + v1 * as_[160 + lane];
    r[3] = v2 * as_[192 + lane] + v3 * as_[224 + lane];
    r[4] = v0 * ad_[lane] + v1 * ad_[32 + lane];
    r[5] = v2 * ad_[64 + lane] + v3 * ad_[96 + lane];
    r[6] = v0 * ad_[128 + lane] + v1 * ad_[160 + lane];
    r[7] = v2 * ad_[192 + lane] + v3 * ad_[224 + lane];
#pragma unroll
    for (int k = 0; k < 8; k++) r[k] = warp_sum(r[k]);
    if (lane == 0) {
#pragma unroll
        for (int k = 0; k < 8; k++) g_att[n * 8 + k] = r[k];
    }
}

// ---------------- edge softmax + aggregation (atomic-free, warp per dst node) ----------------
__global__ void agg_kernel(int t) {
    int wid = threadIdx.x >> 5, lane = threadIdx.x & 31;
    int n = blockIdx.x * 8 + wid;
    if (n >= NN) return;
    float* outp = t ? g_out1 : g_out0;
    int base = g_rowptr[t * (NN + 1) + n];
    int deg = g_rowptr[t * (NN + 1) + n + 1] - base;
    float ad0 = g_att[n * 8 + 4 + 2 * t];
    float ad1 = g_att[n * 8 + 5 + 2 * t];

    float m0 = -3.0e38f, m1 = -3.0e38f;
    for (int j = lane; j < deg; j += 32) {
        int src = g_esrc[t * EE + base + j];
        float a0 = leaky(g_att[src * 8 + 2 * t] + ad0);
        float a1 = leaky(g_att[src * 8 + 2 * t + 1] + ad1);
        m0 = fmaxf(m0, a0);
        m1 = fmaxf(m1, a1);
    }
    m0 = warp_max(m0);
    m1 = warp_max(m1);

    float s0 = 0.f, s1 = 0.f;
    float acc0 = 0.f, acc1 = 0.f, acc2 = 0.f, acc3 = 0.f;
    for (int j = 0; j < deg; j++) {
        int src = g_esrc[t * EE + base + j];
        float w0 = expf(leaky(g_att[src * 8 + 2 * t] + ad0) - m0);
        float w1 = expf(leaky(g_att[src * 8 + 2 * t + 1] + ad1) - m1);
        s0 += w0;
        s1 += w1;
        const float* hr = g_h + (size_t)src * CC;
        acc0 += w0 * hr[lane];
        acc1 += w0 * hr[32 + lane];
        acc2 += w1 * hr[64 + lane];
        acc3 += w1 * hr[96 + lane];
    }
    float r0 = 1.f / (s0 + 1e-16f);
    float r1 = 1.f / (s1 + 1e-16f);
    float* orow = outp + (size_t)n * CC;
    orow[lane] = fmaxf(acc0 * r0, 0.f);
    orow[32 + lane] = fmaxf(acc1 * r0, 0.f);
    orow[64 + lane] = fmaxf(acc2 * r1, 0.f);
    orow[96 + lane] = fmaxf(acc3 * r1, 0.f);
}

// ---------------- weighted combine + ReLU ----------------
__global__ void combine_kernel(int sbase) {
    int idx = blockIdx.x * blockDim.x + threadIdx.x;
    if (idx >= NN * CC / 4) return;
    float s0 = g_scores[sbase] * (1.f / NN);
    float s1 = g_scores[sbase + 1] * (1.f / NN);
    float m = fmaxf(s0, s1);
    float e0 = expf(s0 - m), e1 = expf(s1 - m);
    float a0 = e0 / (e0 + e1);
    float a1 = 1.f - a0;
    float4 v0 = reinterpret_cast<const float4*>(g_out0)[idx];
    float4 v1 = reinterpret_cast<const float4*>(g_out1)[idx];
    float4 r;
    r.x = fmaxf(a0 * v0.x + a1 * v1.x, 0.f);
    r.y = fmaxf(a0 * v0.y + a1 * v1.y, 0.f);
    r.z = fmaxf(a0 * v0.z + a1 * v1.z, 0.f);
    r.w = fmaxf(a0 * v0.w + a1 * v1.w, 0.f);
    reinterpret_cast<float4*>(g_comb)[idx] = r;
}

// ---------------- final linear ----------------
__global__ void final_kernel(const float* __restrict__ lw, const float* __restrict__ lb,
                             float* __restrict__ out) {
    int i = blockIdx.x * blockDim.x + threadIdx.x;
    if (i >= NN * OO) return;
    int n = i >> 3, o = i & 7;
    float acc = lb[o];
    const float* row = g_comb + (size_t)n * CC;
#pragma unroll 8
    for (int c = 0; c < CC; c++) acc += row[c] * lw[c * OO + o];
    out[i] = acc;
}

// ---------------- launch ----------------
extern "C" void kernel_launch(void* const* d_in, const int* in_sizes, int n_in,
                              void* d_out, int out_size) {
    const float *x = 0, *p1w = 0, *p1b = 0, *p1as = 0, *p1ad = 0, *p1q = 0, *p1kw = 0, *p1kb = 0;
    const float *p2w = 0, *p2b = 0, *p2as = 0, *p2ad = 0, *p2q = 0, *p2kw = 0, *p2kb = 0;
    const float *linw = 0, *linb = 0;
    const int *ei0 = 0, *ei1 = 0;
    int nEi = 0, n16k = 0, n256 = 0, n128 = 0;
    for (int i = 0; i < n_in; i++) {
        const float* fp = (const float*)d_in[i];
        switch (in_sizes[i]) {
            case NN * FIN: x = fp; break;
            case 2 * EE:
                if (nEi == 0) ei0 = (const int*)d_in[i];
                else ei1 = (const int*)d_in[i];
                nEi++;
                break;
            case FIN * CC: p1w = fp; break;
            case CC * CC:
                if (n16k == 0) p1kw = fp;
                else if (n16k == 1) p2w = fp;
                else p2kw = fp;
                n16k++;
                break;
            case 256:
                if (n256 == 0) p1as = fp;
                else if (n256 == 1) p1ad = fp;
                else if (n256 == 2) p2as = fp;
                else p2ad = fp;
                n256++;
                break;
            case CC:
                if (n128 == 0) p1b = fp;
                else if (n128 == 1) p1q = fp;
                else if (n128 == 2) p1kb = fp;
                else if (n128 == 3) p2b = fp;
                else if (n128 == 4) p2q = fp;
                else p2kb = fp;
                n128++;
                break;
            case CC * OO: linw = fp; break;
            case OO: linb = fp; break;
            default: break;
        }
    }

    const int GRID_MM = (NN + 127) / 128;       // 782
    const int GRID_NODE = (NN + 7) / 8;         // 12500
    const int GRID_EDGE = (2 * EE + 255) / 256; // 4688

    zero_kernel<<<(2 * NN + 255) / 256, 256>>>();
    hist_kernel<<<GRID_EDGE, 256>>>(ei0, ei1);
    scan_kernel<<<2, 1024>>>();
    scatter_kernel<<<GRID_EDGE, 256>>>(ei0, ei1);

    // ---- layer 1 ----
    mm_kernel<FIN, 0, 1><<<GRID_MM, 256>>>(x, p1w, p1b, nullptr, 0);
    att_kernel<<<GRID_NODE, 256>>>(p1as, p1ad);
    agg_kernel<<<GRID_NODE, 256>>>(0);
    agg_kernel<<<GRID_NODE, 256>>>(1);
    mm_kernel<CC, 1, 0><<<dim3(GRID_MM, 2), 256>>>(nullptr, p1kw, p1kb, p1q, 0);
    combine_kernel<<<(NN * CC / 4 + 255) / 256, 256>>>(0);

    // ---- layer 2 ----
    mm_kernel<CC, 0, 1><<<GRID_MM, 256>>>(nullptr, p2w, p2b, nullptr, 0);
    att_kernel<<<GRID_NODE, 256>>>(p2as, p2ad);
    agg_kernel<<<GRID_NODE, 256>>>(0);
    agg_kernel<<<GRID_NODE, 256>>>(1);
    mm_kernel<CC, 1, 0><<<dim3(GRID_MM, 2), 256>>>(nullptr, p2kw, p2kb, p2q, 2);
    combine_kernel<<<(NN * CC / 4 + 255) / 256, 256>>>(2);

    // ---- classifier ----
    final_kernel<<<(NN * OO + 255) / 256, 256>>>(linw, linb, (float*)d_out);
}